// round 16
// baseline (speedup 1.0000x reference)
#include <cuda_runtime.h>
#include <cuda_fp16.h>
#include <math.h>
#include <stdint.h>

#define NTOK 8192
#define DDIM 1024
#define HDIM 4096
#define NEXP 8
#define NPAIR (NTOK * 2)
#define MAXENT 136
#define MAXT   3072

// ---------------- scratch (device globals: allocation-free rule) ----------------
__device__ __half gXh[(size_t)NTOK * DDIM];
__device__ __half gH[(size_t)NPAIR * HDIM];
__device__ __half gW1h[(size_t)NEXP * DDIM * HDIM];
__device__ __half gW2h[(size_t)NEXP * HDIM * DDIM];
__device__ __half g_ys[(size_t)NPAIR * DDIM];   // fp16 gated expert outputs
__device__ int   g_tl[NPAIR];
__device__ float g_gl[NPAIR];
__device__ int   g_counts[NEXP];
__device__ int   g_offsets[NEXP + 1];
__device__ int   g_cursor[NEXP];
__device__ int   g_tok_e[NTOK];
__device__ float g_tok_g[NTOK * 2];
__device__ int   g_ent[MAXENT];     // e<<8 | mTile
__device__ int   g_ready[MAXENT];   // GEMM1 n-tiles done per entry
__device__ int   g_w2r[32];         // W2 quarters done per (e*4+nb), target 4
__device__ int   g_ne;
__device__ int   g_tc;
__device__ int   g_tiles[MAXT];     // type<<28 | payload
__device__ int   g_nt;

// ---------------- helpers ----------------
__device__ __forceinline__ uint32_t hpack2(float a, float b) {
    __half2 h = __floats2half2_rn(a, b);
    return *(uint32_t*)&h;
}

// ---------------- launch 1: zero meta ----------------
__global__ void zero_meta_kernel() {
    int i = threadIdx.x;
    if (i < NEXP) { g_counts[i] = 0; g_cursor[i] = 0; }
    if (i < MAXENT) g_ready[i] = 0;
    if (i < 32) g_w2r[i] = 0;
    if (i == 0) g_tc = 0;
}

// ---------------- launch 2: prep (W1 split | X split | router) ----------------
#define PB_W1 32768
#define PB_X  40960
#define PB_RT 41984

__global__ __launch_bounds__(256)
void prep_kernel(const float* __restrict__ x, const float* __restrict__ noisep,
                 const float* __restrict__ Wr, const float* __restrict__ Wn,
                 const float* __restrict__ W1) {
    int b = blockIdx.x, tid = threadIdx.x;
    if (b < PB_W1) {
        size_t i = ((size_t)b * 256 + tid);
        float4 v = ((const float4*)W1)[i];
        *(uint2*)(gW1h + i * 4) = make_uint2(hpack2(v.x, v.y), hpack2(v.z, v.w));
    } else if (b < PB_X) {
        int t = b - PB_W1;
        float4 v = ((const float4*)(x + (size_t)t * DDIM))[tid];
        size_t o = (size_t)t * DDIM + tid * 4;
        *(uint2*)(gXh + o) = make_uint2(hpack2(v.x, v.y), hpack2(v.z, v.w));
    } else {
        // router: one warp per token
        int warp = tid >> 5, lane = tid & 31;
        int t = (b - PB_X) * 8 + warp;
        const float* xr = x + (size_t)t * DDIM;
        float xs[32];
#pragma unroll
        for (int i = 0; i < 32; i++) xs[i] = xr[lane + 32 * i];
        float nz[NEXP];
#pragma unroll
        for (int e = 0; e < NEXP; e++) {
            const float* wr = Wr + e * DDIM;
            const float* wn = Wn + e * DDIM;
            float a = 0.f, bb = 0.f;
#pragma unroll
            for (int i = 0; i < 32; i++) {
                float xv = xs[i];
                a  = fmaf(xv, wr[lane + 32 * i], a);
                bb = fmaf(xv, wn[lane + 32 * i], bb);
            }
#pragma unroll
            for (int o = 16; o > 0; o >>= 1) {
                a  += __shfl_xor_sync(0xffffffffu, a, o);
                bb += __shfl_xor_sync(0xffffffffu, bb, o);
            }
            float sp = fmaxf(bb, 0.f) + log1pf(expf(-fabsf(bb)));
            nz[e] = a + noisep[t * NEXP + e] * sp;
        }
        if (lane == 0) {
            int e0 = 0; float v0 = nz[0];
#pragma unroll
            for (int e = 1; e < NEXP; e++) if (nz[e] > v0) { v0 = nz[e]; e0 = e; }
            int e1 = (e0 == 0) ? 1 : 0; float v1 = nz[e1];
#pragma unroll
            for (int e = 0; e < NEXP; e++)
                if (e != e0 && nz[e] > v1) { v1 = nz[e]; e1 = e; }
            float m  = fmaxf(v0, v1);
            float z0 = expf(v0 - m), z1 = expf(v1 - m);
            float inv = 1.f / (z0 + z1);
            g_tok_e[t] = e0 | (e1 << 8);
            g_tok_g[t * 2 + 0] = z0 * inv;
            g_tok_g[t * 2 + 1] = z1 * inv;
            atomicAdd(&g_counts[e0], 1);
            atomicAdd(&g_counts[e1], 1);
        }
    }
}

// ---------------- launch 3: scan + lists + tile schedule ----------------
__global__ void scanbuild_kernel() {
    int tid = threadIdx.x;
    if (tid == 0) {
        int s = 0;
        for (int e = 0; e < NEXP; e++) { g_offsets[e] = s; s += g_counts[e]; }
        g_offsets[NEXP] = s;
        int ne = 0;
        for (int e = 0; e < NEXP; e++)
            for (int m = 0; m * 128 < g_counts[e]; m++)
                g_ent[ne++] = (e << 8) | m;
        g_ne = ne;
        // tile list: W2 quarters INTERLEAVED into GEMM1 (1 per 8), then GEMM2
        int p = 0, w2 = 0;
        int g1 = ne * 16;
        for (int j = 0; j < g1; j++) {
            if ((j & 7) == 0 && w2 < 128) g_tiles[p++] = (2 << 28) | w2++;
            g_tiles[p++] = (3 << 28) | j;
        }
        while (w2 < 128) g_tiles[p++] = (2 << 28) | w2++;
        for (int j = 0; j < ne * 4; j++) g_tiles[p++] = (4 << 28) | j;
        g_nt = p;
    }
    __syncthreads();
    for (int t = tid; t < NTOK; t += 1024) {
        int ee = g_tok_e[t];
        int e0 = ee & 0xff, e1 = ee >> 8;
        int s  = atomicAdd(&g_cursor[e0], 1);
        int i0 = g_offsets[e0] + s;
        g_tl[i0] = t * 2;     g_gl[i0] = g_tok_g[t * 2];
        s = atomicAdd(&g_cursor[e1], 1);
        int i1 = g_offsets[e1] + s;
        g_tl[i1] = t * 2 + 1; g_gl[i1] = g_tok_g[t * 2 + 1];
    }
}

// ---------------- mma helpers ----------------
__device__ __forceinline__ void ldsm4(uint32_t (&r)[4], uint32_t a) {
    asm volatile("ldmatrix.sync.aligned.m8n8.x4.shared.b16 {%0,%1,%2,%3}, [%4];\n"
                 : "=r"(r[0]), "=r"(r[1]), "=r"(r[2]), "=r"(r[3]) : "r"(a));
}
__device__ __forceinline__ void ldsm4t(uint32_t (&r)[4], uint32_t a) {
    asm volatile("ldmatrix.sync.aligned.m8n8.x4.trans.shared.b16 {%0,%1,%2,%3}, [%4];\n"
                 : "=r"(r[0]), "=r"(r[1]), "=r"(r[2]), "=r"(r[3]) : "r"(a));
}
__device__ __forceinline__ void mma16816(float (&c)[4], const uint32_t (&a)[4],
                                         uint32_t b0, uint32_t b1) {
    asm volatile(
        "mma.sync.aligned.m16n8k16.row.col.f32.f16.f16.f32 "
        "{%0,%1,%2,%3},{%4,%5,%6,%7},{%8,%9},{%0,%1,%2,%3};\n"
        : "+f"(c[0]), "+f"(c[1]), "+f"(c[2]), "+f"(c[3])
        : "r"(a[0]), "r"(a[1]), "r"(a[2]), "r"(a[3]), "r"(b0), "r"(b1));
}
__device__ __forceinline__ void cpa16(uint32_t d, const void* s) {
    asm volatile("cp.async.cg.shared.global [%0], [%1], 16;" :: "r"(d), "l"(s)
                 : "memory");
}
__device__ __forceinline__ void cpa_commit() {
    asm volatile("cp.async.commit_group;" ::: "memory");
}
__device__ __forceinline__ void cpa_wait2() {
    asm volatile("cp.async.wait_group 2;" ::: "memory");
}
__device__ __forceinline__ void spin_ge(int* p, int target) {
    while (atomicAdd(p, 0) < target) __nanosleep(64);
}

// smem geometry: CTA tile 128(M) x 256(N), BK=64. conflict-free pitches.
#define A_BYTES 18432
#define B_PITCH 528
#define B_BYTES (64 * B_PITCH)
#define STG     (A_BYTES + B_BYTES)
#define NSTAGE  4
#define DSMEM   (NSTAGE * STG)

// ---------------- launch 4: fused persistent scheduler ----------------
// tile types: 2=W2-split quarter (pl = e<<4 | nb<<2 | kq)
//             3=GEMM1 (pl = eidx<<4 | n16)   4=GEMM2 (pl = eidx<<2 | n4)
__global__ __launch_bounds__(256, 1)
void moe_fused(const float* __restrict__ W2) {
    extern __shared__ char dsm[];
    const uint32_t ab = (uint32_t)__cvta_generic_to_shared(dsm);
    __shared__ int s_tile;

    const int tid = threadIdx.x;
    const int warp = tid >> 5, lane = tid & 31;
    const int aC = tid & 7,  aR = tid >> 3;
    const int bC = tid & 31, bR = tid >> 5;
    const int wm = (warp >> 2) * 64;          // 2(M) x 4(N) warp grid, 64x64
    const int wn = (warp & 3) * 64;
    const int aRow  = lane & 15;
    const int aCol  = (lane >> 4) << 3;
    const int bRowL = ((lane >> 3) & 1) * 8 + (lane & 7);
    const int bColL = (lane >> 4) * 8;

    for (;;) {
        if (tid == 0) s_tile = atomicAdd(&g_tc, 1);
        __syncthreads();                       // publish s_tile; fence smem reuse
        const int it = s_tile;
        if (it >= g_nt) break;
        const int tl = g_tiles[it];
        const int ty = tl >> 28;
        const int pl = tl & 0x0FFFFFFF;

        if (ty == 2) {                         // W2 quarter: 1024 k-rows x 256 n
            int e = pl >> 4, nbi = (pl >> 2) & 3, kq = pl & 3;
            size_t base = ((size_t)e * HDIM + kq * 1024) * DDIM + nbi * 256;
            for (int j0 = 0; j0 < 65536; j0 += 1024) {
                float4 v[4]; size_t oo[4];
#pragma unroll
                for (int q = 0; q < 4; q++) {
                    int j = j0 + q * 256 + tid;
                    oo[q] = base + (size_t)(j >> 6) * DDIM + (j & 63) * 4;
                    v[q] = *(const float4*)(W2 + oo[q]);
                }
#pragma unroll
                for (int q = 0; q < 4; q++)
                    *(uint2*)(gW2h + oo[q]) =
                        make_uint2(hpack2(v[q].x, v[q].y), hpack2(v[q].z, v[q].w));
            }
            __threadfence(); __syncthreads();
            if (tid == 0) atomicAdd(&g_w2r[e * 4 + nbi], 1);
            continue;
        }

        // ---------------- GEMM tile ----------------
        const int mode = (ty == 4);
        int eidx, nbi;
        if (!mode) { eidx = pl >> 4; nbi = pl & 15; }
        else       { eidx = pl >> 2; nbi = pl & 3; }
        const int nb  = nbi * 256;
        const int ent = g_ent[eidx];
        const int e = ent >> 8, mT = ent & 255;
        const int off = g_offsets[e], cnt = g_counts[e];

        if (mode) {                            // gate on h rows + W2 block
            if (tid == 0) {
                spin_ge(&g_ready[eidx], 16);
                spin_ge(&g_w2r[e * 4 + nbi], 4);
            }
            __syncthreads();
            __threadfence();                   // acquire
        }

        const int K   = mode ? HDIM : DDIM;
        const int NGL = mode ? DDIM : HDIM;
        const int NC  = K / 64;
        const __half* Ah = mode ? gH : gXh;
        const __half* Bh = (mode ? gW2h : gW1h) + (size_t)e * DDIM * HDIM;

        uint32_t aSrc[4], aDst[4];
#pragma unroll
        for (int q = 0; q < 4; q++) {
            int r  = aR + q * 32;
            int rm = min(mT * 128 + r, cnt - 1);
            uint32_t rowbase = mode ? (uint32_t)(off + rm) * HDIM
                                    : (uint32_t)(g_tl[off + rm] >> 1) * DDIM;
            aSrc[q] = rowbase + aC * 8;
            aDst[q] = (uint32_t)(r * 144 + aC * 16);
        }
        uint32_t bSrc[4], bDst[4], bSrc2[4], bDst2[4];
#pragma unroll
        for (int q = 0; q < 4; q++) {
            int r = bR + q * 8;
            bSrc[q]  = (uint32_t)(r * NGL + nb + bC * 8);
            bDst[q]  = (uint32_t)(r * B_PITCH + bC * 16);
            bSrc2[q] = (uint32_t)((r + 32) * NGL + nb + bC * 8);
            bDst2[q] = (uint32_t)((r + 32) * B_PITCH + bC * 16);
        }

        auto ldc = [&](int c) {
            uint32_t sb = ab + (uint32_t)(c % NSTAGE) * STG;
            uint32_t k0 = c * 64;
#pragma unroll
            for (int q = 0; q < 4; q++)
                cpa16(sb + aDst[q], Ah + aSrc[q] + k0);
            uint32_t bk = k0 * (uint32_t)NGL;
#pragma unroll
            for (int q = 0; q < 4; q++)
                cpa16(sb + A_BYTES + bDst[q], Bh + bSrc[q] + bk);
#pragma unroll
            for (int q = 0; q < 4; q++)
                cpa16(sb + A_BYTES + bDst2[q], Bh + bSrc2[q] + bk);
            cpa_commit();
        };

        float acc[4][8][4];
#pragma unroll
        for (int a = 0; a < 4; a++)
#pragma unroll
            for (int b = 0; b < 8; b++)
#pragma unroll
                for (int c = 0; c < 4; c++) acc[a][b][c] = 0.f;

        auto compute = [&](int c) {
            uint32_t sb = ab + (uint32_t)(c % NSTAGE) * STG;
#pragma unroll
            for (int ks = 0; ks < 4; ks++) {
                uint32_t afh[4][4];
#pragma unroll
                for (int ms = 0; ms < 4; ms++)
                    ldsm4(afh[ms], sb + (uint32_t)((wm + ms * 16 + aRow) * 144 +
                                                   (ks * 16 + aCol) * 2));
#pragma unroll
                for (int g = 0; g < 4; g++) {
                    uint32_t brow = (uint32_t)((ks * 16 + bRowL) * B_PITCH +
                                               (wn + g * 16 + bColL) * 2);
                    uint32_t qh[4];
                    ldsm4t(qh, sb + A_BYTES + brow);
#pragma unroll
                    for (int ms = 0; ms < 4; ms++) {
                        mma16816(acc[ms][g * 2 + 0], afh[ms], qh[0], qh[1]);
                        mma16816(acc[ms][g * 2 + 1], afh[ms], qh[2], qh[3]);
                    }
                }
            }
        };

        ldc(0); ldc(1); ldc(2);
        for (int c = 0; c < NC; c++) {
            cpa_wait2();
            __syncthreads();
            if (c + 3 < NC) ldc(c + 3); else cpa_commit();
            compute(c);
        }

        // ---------------- epilogue ----------------
#pragma unroll
        for (int ms = 0; ms < 4; ms++) {
            int r0 = wm + ms * 16 + (lane >> 2);
#pragma unroll
            for (int half = 0; half < 2; half++) {
                int r  = r0 + half * 8;
                int gm = mT * 128 + r;
                if (gm < cnt) {
                    int idx = off + gm;
                    if (!mode) {
                        __half* oh = gH + (size_t)idx * HDIM + nb;
#pragma unroll
                        for (int ns = 0; ns < 8; ns++) {
                            int cc  = wn + ns * 8 + (lane & 3) * 2;
                            float v0 = fmaxf(acc[ms][ns][half * 2 + 0], 0.f);
                            float v1 = fmaxf(acc[ms][ns][half * 2 + 1], 0.f);
                            v0 *= v0; v1 *= v1;
                            *(uint32_t*)(oh + cc) = hpack2(v0, v1);
                        }
                    } else {
                        int   pr = g_tl[idx];
                        float gt = g_gl[idx];
                        __half* yo = g_ys + (size_t)pr * DDIM + nb;
#pragma unroll
                        for (int ns = 0; ns < 8; ns++) {
                            int cc = wn + ns * 8 + (lane & 3) * 2;
                            *(uint32_t*)(yo + cc) =
                                hpack2(acc[ms][ns][half * 2 + 0] * gt,
                                       acc[ms][ns][half * 2 + 1] * gt);
                        }
                    }
                }
            }
        }

        if (!mode) {                           // release h rows for GEMM2
            __threadfence();
            __syncthreads();
            if (tid == 0) atomicAdd(&g_ready[eidx], 1);
        }
    }
}

__global__ void combine_kernel(float* __restrict__ out) {
    size_t i = (size_t)blockIdx.x * blockDim.x + threadIdx.x;  // 4-float group
    size_t t = i >> 8;          // DDIM/4 = 256 groups per token
    size_t d4 = (i & 255) * 4;
    const __half* y0 = g_ys + (t * 2 + 0) * DDIM + d4;
    const __half* y1 = g_ys + (t * 2 + 1) * DDIM + d4;
    uint2 a = *(const uint2*)y0;
    uint2 b = *(const uint2*)y1;
    __half2 a0 = *(__half2*)&a.x, a1 = *(__half2*)&a.y;
    __half2 b0 = *(__half2*)&b.x, b1 = *(__half2*)&b.y;
    float2 s0 = __half22float2(a0), s1 = __half22float2(a1);
    float2 u0 = __half22float2(b0), u1 = __half22float2(b1);
    ((float4*)out)[i] = make_float4(s0.x + u0.x, s0.y + u0.y,
                                    s1.x + u1.x, s1.y + u1.y);
}

// ---------------- launcher ----------------
extern "C" void kernel_launch(void* const* d_in, const int* in_sizes, int n_in,
                              void* d_out, int out_size) {
    const float* x  = (const float*)d_in[0];
    const float* nz = (const float*)d_in[1];
    const float* Wr = (const float*)d_in[2];
    const float* Wn = (const float*)d_in[3];
    const float* W1 = (const float*)d_in[4];
    const float* W2 = (const float*)d_in[5];
    float* out = (float*)d_out;

    cudaFuncSetAttribute(moe_fused, cudaFuncAttributeMaxDynamicSharedMemorySize,
                         DSMEM);

    zero_meta_kernel<<<1, 256>>>();                                  // 1
    prep_kernel<<<PB_RT, 256>>>(x, nz, Wr, Wn, W1);                  // 2
    scanbuild_kernel<<<1, 1024>>>();                                 // 3
    // 4 (profiled): persistent interleaved W2-split + GEMM1 + GEMM2
    moe_fused<<<152, 256, DSMEM>>>(W2);
    combine_kernel<<<(NTOK * DDIM / 4) / 256, 256>>>(out);           // 5
}

// round 17
// speedup vs baseline: 1.0225x; 1.0225x over previous
#include <cuda_runtime.h>
#include <cuda_fp16.h>
#include <math.h>
#include <stdint.h>

#define NTOK 8192
#define DDIM 1024
#define HDIM 4096
#define NEXP 8
#define NPAIR (NTOK * 2)
#define MAXENT 136
#define MAXT   3072

// ---------------- scratch (device globals: allocation-free rule) ----------------
__device__ __half gXh[(size_t)NTOK * DDIM];
__device__ __half gH[(size_t)NPAIR * HDIM];
__device__ __half gW1h[(size_t)NEXP * DDIM * HDIM];
__device__ __half gW2h[(size_t)NEXP * HDIM * DDIM];
__device__ __half g_ys[(size_t)NPAIR * DDIM];   // fp16 gated expert outputs
__device__ int   g_tl[NPAIR];
__device__ float g_gl[NPAIR];
__device__ int   g_counts[NEXP];
__device__ int   g_offsets[NEXP + 1];
__device__ int   g_cursor[NEXP];
__device__ int   g_tok_e[NTOK];
__device__ float g_tok_g[NTOK * 2];
__device__ int   g_ent[MAXENT];     // e<<8 | mTile
__device__ int   g_ready[MAXENT];   // GEMM1 n-tiles done per entry
__device__ int   g_w2r[32];         // W2 quarters done per (e*4+nb), target 4
__device__ int   g_ne;
__device__ int   g_tc;
__device__ int   g_tiles[MAXT];     // type<<28 | payload
__device__ int   g_nt;

// ---------------- helpers ----------------
__device__ __forceinline__ uint32_t hpack2(float a, float b) {
    __half2 h = __floats2half2_rn(a, b);
    return *(uint32_t*)&h;
}

// ---------------- launch 1: zero meta ----------------
__global__ void zero_meta_kernel() {
    int i = threadIdx.x;
    if (i < NEXP) { g_counts[i] = 0; g_cursor[i] = 0; }
    if (i < MAXENT) g_ready[i] = 0;
    if (i < 32) g_w2r[i] = 0;
    if (i == 0) g_tc = 0;
}

// ---------------- launch 2: prep (W1 split | X split | router), MLP=4 --------
#define PB_W1 8192            // 8192 blocks x 1024 float4 = all of W1
#define PB_X  10240           // 2048 blocks x 1024 float4 = all of x
#define PB_RT 11264           // 1024 router blocks (8 warps = 8 tokens each)

__global__ __launch_bounds__(256)
void prep_kernel(const float* __restrict__ x, const float* __restrict__ noisep,
                 const float* __restrict__ Wr, const float* __restrict__ Wn,
                 const float* __restrict__ W1) {
    int b = blockIdx.x, tid = threadIdx.x;
    if (b < PB_X) {
        const float4* src;
        __half* dst;
        size_t base;
        if (b < PB_W1) { src = (const float4*)W1; dst = gW1h;
                         base = (size_t)b * 1024 + tid; }
        else           { src = (const float4*)x;  dst = gXh;
                         base = (size_t)(b - PB_W1) * 1024 + tid; }
        float4 v[4];
#pragma unroll
        for (int q = 0; q < 4; q++) v[q] = src[base + q * 256];   // 4 LDG in flight
#pragma unroll
        for (int q = 0; q < 4; q++) {
            size_t i = base + q * 256;
            *(uint2*)(dst + i * 4) =
                make_uint2(hpack2(v[q].x, v[q].y), hpack2(v[q].z, v[q].w));
        }
    } else {
        // router: one warp per token
        int warp = tid >> 5, lane = tid & 31;
        int t = (b - PB_X) * 8 + warp;
        const float* xr = x + (size_t)t * DDIM;
        float xs[32];
#pragma unroll
        for (int i = 0; i < 32; i++) xs[i] = xr[lane + 32 * i];
        float nz[NEXP];
#pragma unroll
        for (int e = 0; e < NEXP; e++) {
            const float* wr = Wr + e * DDIM;
            const float* wn = Wn + e * DDIM;
            float a = 0.f, bb = 0.f;
#pragma unroll
            for (int i = 0; i < 32; i++) {
                float xv = xs[i];
                a  = fmaf(xv, wr[lane + 32 * i], a);
                bb = fmaf(xv, wn[lane + 32 * i], bb);
            }
#pragma unroll
            for (int o = 16; o > 0; o >>= 1) {
                a  += __shfl_xor_sync(0xffffffffu, a, o);
                bb += __shfl_xor_sync(0xffffffffu, bb, o);
            }
            float sp = fmaxf(bb, 0.f) + log1pf(expf(-fabsf(bb)));
            nz[e] = a + noisep[t * NEXP + e] * sp;
        }
        if (lane == 0) {
            int e0 = 0; float v0 = nz[0];
#pragma unroll
            for (int e = 1; e < NEXP; e++) if (nz[e] > v0) { v0 = nz[e]; e0 = e; }
            int e1 = (e0 == 0) ? 1 : 0; float v1 = nz[e1];
#pragma unroll
            for (int e = 0; e < NEXP; e++)
                if (e != e0 && nz[e] > v1) { v1 = nz[e]; e1 = e; }
            float m  = fmaxf(v0, v1);
            float z0 = expf(v0 - m), z1 = expf(v1 - m);
            float inv = 1.f / (z0 + z1);
            g_tok_e[t] = e0 | (e1 << 8);
            g_tok_g[t * 2 + 0] = z0 * inv;
            g_tok_g[t * 2 + 1] = z1 * inv;
            atomicAdd(&g_counts[e0], 1);
            atomicAdd(&g_counts[e1], 1);
        }
    }
}

// ---------------- launch 3: scan + lists + tile schedule ----------------
__global__ void scanbuild_kernel() {
    int tid = threadIdx.x;
    if (tid == 0) {
        int s = 0;
        for (int e = 0; e < NEXP; e++) { g_offsets[e] = s; s += g_counts[e]; }
        g_offsets[NEXP] = s;
        int ne = 0;
        for (int e = 0; e < NEXP; e++)
            for (int m = 0; m * 128 < g_counts[e]; m++)
                g_ent[ne++] = (e << 8) | m;
        g_ne = ne;
        // tile list: W2 quarters INTERLEAVED into GEMM1 (1 per 8), then GEMM2
        int p = 0, w2 = 0;
        int g1 = ne * 16;
        for (int j = 0; j < g1; j++) {
            if ((j & 7) == 0 && w2 < 128) g_tiles[p++] = (2 << 28) | w2++;
            g_tiles[p++] = (3 << 28) | j;
        }
        while (w2 < 128) g_tiles[p++] = (2 << 28) | w2++;
        for (int j = 0; j < ne * 4; j++) g_tiles[p++] = (4 << 28) | j;
        g_nt = p;
    }
    __syncthreads();
    for (int t = tid; t < NTOK; t += 1024) {
        int ee = g_tok_e[t];
        int e0 = ee & 0xff, e1 = ee >> 8;
        int s  = atomicAdd(&g_cursor[e0], 1);
        int i0 = g_offsets[e0] + s;
        g_tl[i0] = t * 2;     g_gl[i0] = g_tok_g[t * 2];
        s = atomicAdd(&g_cursor[e1], 1);
        int i1 = g_offsets[e1] + s;
        g_tl[i1] = t * 2 + 1; g_gl[i1] = g_tok_g[t * 2 + 1];
    }
}

// ---------------- mma helpers ----------------
__device__ __forceinline__ void ldsm4(uint32_t (&r)[4], uint32_t a) {
    asm volatile("ldmatrix.sync.aligned.m8n8.x4.shared.b16 {%0,%1,%2,%3}, [%4];\n"
                 : "=r"(r[0]), "=r"(r[1]), "=r"(r[2]), "=r"(r[3]) : "r"(a));
}
__device__ __forceinline__ void ldsm4t(uint32_t (&r)[4], uint32_t a) {
    asm volatile("ldmatrix.sync.aligned.m8n8.x4.trans.shared.b16 {%0,%1,%2,%3}, [%4];\n"
                 : "=r"(r[0]), "=r"(r[1]), "=r"(r[2]), "=r"(r[3]) : "r"(a));
}
__device__ __forceinline__ void mma16816(float (&c)[4], const uint32_t (&a)[4],
                                         uint32_t b0, uint32_t b1) {
    asm volatile(
        "mma.sync.aligned.m16n8k16.row.col.f32.f16.f16.f32 "
        "{%0,%1,%2,%3},{%4,%5,%6,%7},{%8,%9},{%0,%1,%2,%3};\n"
        : "+f"(c[0]), "+f"(c[1]), "+f"(c[2]), "+f"(c[3])
        : "r"(a[0]), "r"(a[1]), "r"(a[2]), "r"(a[3]), "r"(b0), "r"(b1));
}
__device__ __forceinline__ void cpa16(uint32_t d, const void* s) {
    asm volatile("cp.async.cg.shared.global [%0], [%1], 16;" :: "r"(d), "l"(s)
                 : "memory");
}
__device__ __forceinline__ void cpa_commit() {
    asm volatile("cp.async.commit_group;" ::: "memory");
}
__device__ __forceinline__ void cpa_wait2() {
    asm volatile("cp.async.wait_group 2;" ::: "memory");
}
__device__ __forceinline__ void spin_ge(int* p, int target) {
    while (atomicAdd(p, 0) < target) __nanosleep(64);
}

// smem geometry: CTA tile 128(M) x 256(N), BK=64. conflict-free pitches.
#define A_BYTES 18432
#define B_PITCH 528
#define B_BYTES (64 * B_PITCH)
#define STG     (A_BYTES + B_BYTES)
#define NSTAGE  4
#define DSMEM   (NSTAGE * STG)

// ---------------- launch 4: fused persistent scheduler ----------------
// tile types: 2=W2-split quarter (pl = e<<4 | nb<<2 | kq)
//             3=GEMM1 (pl = eidx<<4 | n16)   4=GEMM2 (pl = eidx<<2 | n4)
__global__ __launch_bounds__(256, 1)
void moe_fused(const float* __restrict__ W2) {
    extern __shared__ char dsm[];
    const uint32_t ab = (uint32_t)__cvta_generic_to_shared(dsm);
    __shared__ int s_tile;

    const int tid = threadIdx.x;
    const int warp = tid >> 5, lane = tid & 31;
    const int aC = tid & 7,  aR = tid >> 3;
    const int bC = tid & 31, bR = tid >> 5;
    const int wm = (warp >> 2) * 64;          // 2(M) x 4(N) warp grid, 64x64
    const int wn = (warp & 3) * 64;
    const int aRow  = lane & 15;
    const int aCol  = (lane >> 4) << 3;
    const int bRowL = ((lane >> 3) & 1) * 8 + (lane & 7);
    const int bColL = (lane >> 4) * 8;

    for (;;) {
        if (tid == 0) s_tile = atomicAdd(&g_tc, 1);
        __syncthreads();                       // publish s_tile; fence smem reuse
        const int it = s_tile;
        if (it >= g_nt) break;
        const int tl = g_tiles[it];
        const int ty = tl >> 28;
        const int pl = tl & 0x0FFFFFFF;

        if (ty == 2) {                         // W2 quarter: 1024 k-rows x 256 n
            int e = pl >> 4, nbi = (pl >> 2) & 3, kq = pl & 3;
            size_t base = ((size_t)e * HDIM + kq * 1024) * DDIM + nbi * 256;
            for (int j0 = 0; j0 < 65536; j0 += 1024) {
                float4 v[4]; size_t oo[4];
#pragma unroll
                for (int q = 0; q < 4; q++) {
                    int j = j0 + q * 256 + tid;
                    oo[q] = base + (size_t)(j >> 6) * DDIM + (j & 63) * 4;
                    v[q] = *(const float4*)(W2 + oo[q]);
                }
#pragma unroll
                for (int q = 0; q < 4; q++)
                    *(uint2*)(gW2h + oo[q]) =
                        make_uint2(hpack2(v[q].x, v[q].y), hpack2(v[q].z, v[q].w));
            }
            __threadfence(); __syncthreads();
            if (tid == 0) atomicAdd(&g_w2r[e * 4 + nbi], 1);
            continue;
        }

        // ---------------- GEMM tile ----------------
        const int mode = (ty == 4);
        int eidx, nbi;
        if (!mode) { eidx = pl >> 4; nbi = pl & 15; }
        else       { eidx = pl >> 2; nbi = pl & 3; }
        const int nb  = nbi * 256;
        const int ent = g_ent[eidx];
        const int e = ent >> 8, mT = ent & 255;
        const int off = g_offsets[e], cnt = g_counts[e];

        if (mode) {                            // gate on h rows + W2 block
            if (tid == 0) {
                spin_ge(&g_ready[eidx], 16);
                spin_ge(&g_w2r[e * 4 + nbi], 4);
            }
            __syncthreads();
            __threadfence();                   // acquire
        }

        const int K   = mode ? HDIM : DDIM;
        const int NGL = mode ? DDIM : HDIM;
        const int NC  = K / 64;
        const __half* Ah = mode ? gH : gXh;
        const __half* Bh = (mode ? gW2h : gW1h) + (size_t)e * DDIM * HDIM;

        uint32_t aSrc[4], aDst[4];
#pragma unroll
        for (int q = 0; q < 4; q++) {
            int r  = aR + q * 32;
            int rm = min(mT * 128 + r, cnt - 1);
            uint32_t rowbase = mode ? (uint32_t)(off + rm) * HDIM
                                    : (uint32_t)(g_tl[off + rm] >> 1) * DDIM;
            aSrc[q] = rowbase + aC * 8;
            aDst[q] = (uint32_t)(r * 144 + aC * 16);
        }
        uint32_t bSrc[4], bDst[4], bSrc2[4], bDst2[4];
#pragma unroll
        for (int q = 0; q < 4; q++) {
            int r = bR + q * 8;
            bSrc[q]  = (uint32_t)(r * NGL + nb + bC * 8);
            bDst[q]  = (uint32_t)(r * B_PITCH + bC * 16);
            bSrc2[q] = (uint32_t)((r + 32) * NGL + nb + bC * 8);
            bDst2[q] = (uint32_t)((r + 32) * B_PITCH + bC * 16);
        }

        auto ldc = [&](int c) {
            uint32_t sb = ab + (uint32_t)(c % NSTAGE) * STG;
            uint32_t k0 = c * 64;
#pragma unroll
            for (int q = 0; q < 4; q++)
                cpa16(sb + aDst[q], Ah + aSrc[q] + k0);
            uint32_t bk = k0 * (uint32_t)NGL;
#pragma unroll
            for (int q = 0; q < 4; q++)
                cpa16(sb + A_BYTES + bDst[q], Bh + bSrc[q] + bk);
#pragma unroll
            for (int q = 0; q < 4; q++)
                cpa16(sb + A_BYTES + bDst2[q], Bh + bSrc2[q] + bk);
            cpa_commit();
        };

        float acc[4][8][4];
#pragma unroll
        for (int a = 0; a < 4; a++)
#pragma unroll
            for (int b = 0; b < 8; b++)
#pragma unroll
                for (int c = 0; c < 4; c++) acc[a][b][c] = 0.f;

        auto compute = [&](int c) {
            uint32_t sb = ab + (uint32_t)(c % NSTAGE) * STG;
#pragma unroll
            for (int ks = 0; ks < 4; ks++) {
                uint32_t afh[4][4];
#pragma unroll
                for (int ms = 0; ms < 4; ms++)
                    ldsm4(afh[ms], sb + (uint32_t)((wm + ms * 16 + aRow) * 144 +
                                                   (ks * 16 + aCol) * 2));
#pragma unroll
                for (int g = 0; g < 4; g++) {
                    uint32_t brow = (uint32_t)((ks * 16 + bRowL) * B_PITCH +
                                               (wn + g * 16 + bColL) * 2);
                    uint32_t qh[4];
                    ldsm4t(qh, sb + A_BYTES + brow);
#pragma unroll
                    for (int ms = 0; ms < 4; ms++) {
                        mma16816(acc[ms][g * 2 + 0], afh[ms], qh[0], qh[1]);
                        mma16816(acc[ms][g * 2 + 1], afh[ms], qh[2], qh[3]);
                    }
                }
            }
        };

        ldc(0); ldc(1); ldc(2);
        for (int c = 0; c < NC; c++) {
            cpa_wait2();
            __syncthreads();
            if (c + 3 < NC) ldc(c + 3); else cpa_commit();
            compute(c);
        }

        // ---------------- epilogue ----------------
#pragma unroll
        for (int ms = 0; ms < 4; ms++) {
            int r0 = wm + ms * 16 + (lane >> 2);
#pragma unroll
            for (int half = 0; half < 2; half++) {
                int r  = r0 + half * 8;
                int gm = mT * 128 + r;
                if (gm < cnt) {
                    int idx = off + gm;
                    if (!mode) {
                        __half* oh = gH + (size_t)idx * HDIM + nb;
#pragma unroll
                        for (int ns = 0; ns < 8; ns++) {
                            int cc  = wn + ns * 8 + (lane & 3) * 2;
                            float v0 = fmaxf(acc[ms][ns][half * 2 + 0], 0.f);
                            float v1 = fmaxf(acc[ms][ns][half * 2 + 1], 0.f);
                            v0 *= v0; v1 *= v1;
                            *(uint32_t*)(oh + cc) = hpack2(v0, v1);
                        }
                    } else {
                        int   pr = g_tl[idx];
                        float gt = g_gl[idx];
                        __half* yo = g_ys + (size_t)pr * DDIM + nb;
#pragma unroll
                        for (int ns = 0; ns < 8; ns++) {
                            int cc = wn + ns * 8 + (lane & 3) * 2;
                            *(uint32_t*)(yo + cc) =
                                hpack2(acc[ms][ns][half * 2 + 0] * gt,
                                       acc[ms][ns][half * 2 + 1] * gt);
                        }
                    }
                }
            }
        }

        if (!mode) {                           // release h rows for GEMM2
            __threadfence();
            __syncthreads();
            if (tid == 0) atomicAdd(&g_ready[eidx], 1);
        }
    }
}

// ---------------- launch 5: combine (batched, MLP=8) ----------------
__global__ void combine_kernel(float* __restrict__ out) {
    size_t g = ((size_t)blockIdx.x * blockDim.x + threadIdx.x) * 4;  // 4 groups
    uint2 a[4], b[4];
#pragma unroll
    for (int q = 0; q < 4; q++) {
        size_t i = g + q;
        size_t t = i >> 8, d4 = (i & 255) * 4;
        a[q] = *(const uint2*)(g_ys + (t * 2 + 0) * DDIM + d4);
        b[q] = *(const uint2*)(g_ys + (t * 2 + 1) * DDIM + d4);
    }
#pragma unroll
    for (int q = 0; q < 4; q++) {
        float2 s0 = __half22float2(*(__half2*)&a[q].x);
        float2 s1 = __half22float2(*(__half2*)&a[q].y);
        float2 u0 = __half22float2(*(__half2*)&b[q].x);
        float2 u1 = __half22float2(*(__half2*)&b[q].y);
        ((float4*)out)[g + q] = make_float4(s0.x + u0.x, s0.y + u0.y,
                                           s1.x + u1.x, s1.y + u1.y);
    }
}

// ---------------- launcher ----------------
extern "C" void kernel_launch(void* const* d_in, const int* in_sizes, int n_in,
                              void* d_out, int out_size) {
    const float* x  = (const float*)d_in[0];
    const float* nz = (const float*)d_in[1];
    const float* Wr = (const float*)d_in[2];
    const float* Wn = (const float*)d_in[3];
    const float* W1 = (const float*)d_in[4];
    const float* W2 = (const float*)d_in[5];
    float* out = (float*)d_out;

    cudaFuncSetAttribute(moe_fused, cudaFuncAttributeMaxDynamicSharedMemorySize,
                         DSMEM);

    zero_meta_kernel<<<1, 256>>>();                                  // 1
    prep_kernel<<<PB_RT, 256>>>(x, nz, Wr, Wn, W1);                  // 2
    scanbuild_kernel<<<1, 1024>>>();                                 // 3
    // 4 (profiled): persistent interleaved W2-split + GEMM1 + GEMM2
    moe_fused<<<152, 256, DSMEM>>>(W2);
    // 5: combine, 4 float4 groups per thread
    combine_kernel<<<(NTOK * DDIM / 16) / 256, 256>>>(out);
}